// round 4
// baseline (speedup 1.0000x reference)
#include <cuda_runtime.h>
#include <math.h>

// Problem constants
#define BATCH 8
#define SEQ   1024
#define DMODEL 1024
#define NHEAD 16
#define HDIM  64
#define BHN   (BATCH*NHEAD)         // 128
#define ROWS  (BATCH*SEQ)           // 8192

// -------- static device scratch (no runtime allocations allowed) --------
__device__ float g_Wqkv[1024*3072];          // 12 MB packed [D, 3*D]
__device__ float g_bqkv[3072];
__device__ float g_Q[(size_t)BHN*SEQ*HDIM];  // 32 MB  [bh][s][e]
__device__ float g_K[(size_t)BHN*SEQ*HDIM];  // 32 MB
__device__ float g_V[(size_t)BHN*SEQ*HDIM];  // 32 MB
__device__ float g_ctx[(size_t)ROWS*DMODEL]; // 32 MB  [b*S+s][h*64+e]
__device__ int   g_mask_i32;                 // 1 if mask buffer is int32, 0 if uint8

// -------- mask dtype detection (deterministic, capture-safe) --------
// If the bool mask arrives as int32, every 32-bit word is 0 or 1. If it is
// 1-byte bools, the packed words are almost surely >1 somewhere in the first
// 4096 words (16K bools, ~half set).
__global__ void detect_mask_kernel(const int* __restrict__ m) {
    __shared__ int bad;
    if (threadIdx.x == 0) bad = 0;
    __syncthreads();
    int ok = 1;
    for (int i = threadIdx.x; i < 4096; i += 256) {
        int v = m[i];
        if (v != 0 && v != 1) ok = 0;
    }
    if (!ok) atomicOr(&bad, 1);
    __syncthreads();
    if (threadIdx.x == 0) g_mask_i32 = bad ? 0 : 1;
}

// -------- repack Wq/Wk/Wv [H,D,DH] -> g_Wqkv [D, 3*D], biases -> g_bqkv ------
__global__ void repack_kernel(const float* __restrict__ Wq, const float* __restrict__ bq,
                              const float* __restrict__ Wk, const float* __restrict__ bk,
                              const float* __restrict__ Wv, const float* __restrict__ bv) {
    int idx = blockIdx.x * 256 + threadIdx.x;
    if (idx < 3 * 1048576) {
        int sel = idx >> 20;           // 0=Q,1=K,2=V
        int r   = idx & 1048575;
        int h = r >> 16;
        int r2 = r & 65535;
        int d = r2 >> 6;
        int e = r2 & 63;
        const float* W = (sel == 0) ? Wq : (sel == 1 ? Wk : Wv);
        g_Wqkv[(size_t)d * 3072 + (sel << 10) + (h << 6) + e] = W[(h << 16) + (d << 6) + e];
    }
    if (idx < 3072) {
        int sel = idx >> 10;
        int jj = idx & 1023;
        const float* bb = (sel == 0) ? bq : (sel == 1 ? bk : bv);
        g_bqkv[idx] = bb[jj];
    }
}

// -------- generic 128x128x8 sgemm, 256 threads, 8x8 per thread ---------------
// mode 0: A = Aext (inputs [8192x1024]), B = g_Wqkv [1024x3072], bias = g_bqkv,
//         scatter into g_Q/g_K/g_V ([bh][s][e])
// mode 1: A = g_ctx [8192x1024], B = Bext (Wo [1024x1024]), bias = biasext (bo),
//         C = Cext (d_out)
__global__ __launch_bounds__(256) void sgemm128(const float* __restrict__ Aext,
                                                const float* __restrict__ Bext,
                                                const float* __restrict__ biasext,
                                                float* __restrict__ Cext,
                                                int N, int mode) {
    __shared__ __align__(16) float Asm[8][132];
    __shared__ __align__(16) float Bsm[8][128];
    const int K = 1024;
    const float* A = (mode == 0) ? Aext : g_ctx;
    const float* B = (mode == 0) ? g_Wqkv : Bext;

    int tid = threadIdx.x;
    int row0 = blockIdx.y * 128, col0 = blockIdx.x * 128;
    int aRow = tid >> 1, aCol = (tid & 1) * 4;
    int bRow = tid >> 5, bCol = (tid & 31) * 4;
    int tx = tid & 15, ty = tid >> 4;

    float acc[8][8];
#pragma unroll
    for (int i = 0; i < 8; i++)
#pragma unroll
        for (int j = 0; j < 8; j++) acc[i][j] = 0.f;

    const float* Aptr = A + (size_t)(row0 + aRow) * K + aCol;
    const float* Bptr = B + (size_t)bRow * N + col0 + bCol;

    for (int k0 = 0; k0 < K; k0 += 8) {
        float4 av = *(const float4*)(Aptr + k0);
        float4 bv = *(const float4*)(Bptr + (size_t)k0 * N);
        Asm[aCol][aRow] = av.x; Asm[aCol + 1][aRow] = av.y;
        Asm[aCol + 2][aRow] = av.z; Asm[aCol + 3][aRow] = av.w;
        *(float4*)&Bsm[bRow][bCol] = bv;
        __syncthreads();
#pragma unroll
        for (int k = 0; k < 8; k++) {
            float4 a0 = *(const float4*)&Asm[k][ty * 8];
            float4 a1 = *(const float4*)&Asm[k][ty * 8 + 4];
            float4 b0 = *(const float4*)&Bsm[k][tx * 8];
            float4 b1 = *(const float4*)&Bsm[k][tx * 8 + 4];
            float ra[8] = {a0.x, a0.y, a0.z, a0.w, a1.x, a1.y, a1.z, a1.w};
            float rb[8] = {b0.x, b0.y, b0.z, b0.w, b1.x, b1.y, b1.z, b1.w};
#pragma unroll
            for (int i = 0; i < 8; i++)
#pragma unroll
                for (int j = 0; j < 8; j++) acc[i][j] = fmaf(ra[i], rb[j], acc[i][j]);
        }
        __syncthreads();
    }

    if (mode == 0) {
        int sel = col0 >> 10;  // whole 128-col tile lies in one of Q/K/V
        float* dst = (sel == 0) ? g_Q : (sel == 1 ? g_K : g_V);
#pragma unroll
        for (int i = 0; i < 8; i++) {
            int r = row0 + ty * 8 + i;
            int b = r >> 10, s = r & 1023;
#pragma unroll
            for (int j = 0; j < 8; j++) {
                int c = col0 + tx * 8 + j;
                int jj = c & 1023;
                int h = jj >> 6, e = jj & 63;
                dst[((size_t)((b << 4) + h) << 16) + (s << 6) + e] = acc[i][j] + g_bqkv[c];
            }
        }
    } else {
#pragma unroll
        for (int i = 0; i < 8; i++) {
            int r = row0 + ty * 8 + i;
#pragma unroll
            for (int j = 0; j < 8; j++) {
                int c = col0 + tx * 8 + j;
                Cext[(size_t)r * N + c] = acc[i][j] + biasext[c];
            }
        }
    }
}

// -------- fused flash attention, fp32 ----------------------------------------
// One block = 128 query rows of one (b,h). 256 threads, 8x4 register tiles.
// Online softmax over key tiles of 64. Writes ctx in concat-head layout.
// Dynamic smem: Qs[128][65] + Ks[64][65] + Vs[64][65] + Ps[128][65] floats.
#define FA_PITCH 65
#define FA_SMEM_FLOATS (128*FA_PITCH + 64*FA_PITCH + 64*FA_PITCH + 128*FA_PITCH)

__global__ __launch_bounds__(256, 2) void flash_kernel(const unsigned char* __restrict__ m8,
                                                       const int* __restrict__ m32) {
    extern __shared__ float smf[];
    float* Qs = smf;                          // [128][65]
    float* Ks = Qs + 128 * FA_PITCH;          // [64][65]
    float* Vs = Ks + 64 * FA_PITCH;           // [64][65]
    float* Ps = Vs + 64 * FA_PITCH;           // [128][65]

    int tid = threadIdx.x;
    int tx = tid & 15;        // 16 cols groups (x4)
    int ty = tid >> 4;        // 16 row groups (x8)
    int bh = blockIdx.y;
    int b = bh >> 4, h = bh & 15;
    int sq0 = blockIdx.x * 128;

    const float* Qp = g_Q + (size_t)bh * 65536;
    const float* Kp = g_K + (size_t)bh * 65536;
    const float* Vp = g_V + (size_t)bh * 65536;
    int mi32 = g_mask_i32;

    // Load Q tile [128][64] (scalar smem stores, pitch 65)
#pragma unroll
    for (int l = 0; l < 8; l++) {
        int idx = tid + l * 256;
        int r = idx >> 4;
        int c = (idx & 15) * 4;
        float4 v = *(const float4*)(Qp + (size_t)(sq0 + r) * 64 + c);
        float* d = Qs + r * FA_PITCH + c;
        d[0] = v.x; d[1] = v.y; d[2] = v.z; d[3] = v.w;
    }

    float acc[8][4];
    float mrow[8], lrow[8];
#pragma unroll
    for (int i = 0; i < 8; i++) {
        mrow[i] = -INFINITY; lrow[i] = 0.f;
#pragma unroll
        for (int j = 0; j < 4; j++) acc[i][j] = 0.f;
    }

    for (int sk0 = 0; sk0 < SEQ; sk0 += 64) {
        // Load K and V tiles [64][64]
#pragma unroll
        for (int l = 0; l < 4; l++) {
            int idx = tid + l * 256;
            int r = idx >> 4;
            int c = (idx & 15) * 4;
            float4 kv = *(const float4*)(Kp + (size_t)(sk0 + r) * 64 + c);
            float* dk = Ks + r * FA_PITCH + c;
            dk[0] = kv.x; dk[1] = kv.y; dk[2] = kv.z; dk[3] = kv.w;
            float4 vv = *(const float4*)(Vp + (size_t)(sk0 + r) * 64 + c);
            float* dv = Vs + r * FA_PITCH + c;
            dv[0] = vv.x; dv[1] = vv.y; dv[2] = vv.z; dv[3] = vv.w;
        }
        __syncthreads();

        // S = Q K^T (8x4 per thread)
        float s[8][4];
#pragma unroll
        for (int i = 0; i < 8; i++)
#pragma unroll
            for (int j = 0; j < 4; j++) s[i][j] = 0.f;
#pragma unroll 4
        for (int e = 0; e < 64; e++) {
            float qa[8], kb[4];
#pragma unroll
            for (int i = 0; i < 8; i++) qa[i] = Qs[(ty * 8 + i) * FA_PITCH + e];
#pragma unroll
            for (int j = 0; j < 4; j++) kb[j] = Ks[(tx * 4 + j) * FA_PITCH + e];
#pragma unroll
            for (int i = 0; i < 8; i++)
#pragma unroll
                for (int j = 0; j < 4; j++) s[i][j] = fmaf(qa[i], kb[j], s[i][j]);
        }

        // mask + scale + online softmax (per row: reduce over the 16 tx lanes)
        const float scale = 0.03125f;  // 1/sqrt(1024)
        float alpha[8];
#pragma unroll
        for (int i = 0; i < 8; i++) {
            size_t midx = ((size_t)b << 20) + ((size_t)(sq0 + ty * 8 + i) << 10) + sk0 + tx * 4;
            int mv[4];
            if (mi32) {
                int4 mm = *(const int4*)(m32 + midx);
                mv[0] = mm.x; mv[1] = mm.y; mv[2] = mm.z; mv[3] = mm.w;
            } else {
                uchar4 mm = *(const uchar4*)(m8 + midx);
                mv[0] = mm.x; mv[1] = mm.y; mv[2] = mm.z; mv[3] = mm.w;
            }
#pragma unroll
            for (int j = 0; j < 4; j++) s[i][j] = mv[j] ? -1e9f : s[i][j] * scale;

            float rmax = fmaxf(fmaxf(s[i][0], s[i][1]), fmaxf(s[i][2], s[i][3]));
#pragma unroll
            for (int o = 1; o < 16; o <<= 1)
                rmax = fmaxf(rmax, __shfl_xor_sync(0xFFFFFFFFu, rmax, o));
            float mnew = fmaxf(mrow[i], rmax);
            alpha[i] = __expf(mrow[i] - mnew);
            mrow[i] = mnew;
            float rsum = 0.f;
#pragma unroll
            for (int j = 0; j < 4; j++) {
                s[i][j] = __expf(s[i][j] - mnew);
                rsum += s[i][j];
            }
#pragma unroll
            for (int o = 1; o < 16; o <<= 1)
                rsum += __shfl_xor_sync(0xFFFFFFFFu, rsum, o);
            lrow[i] = lrow[i] * alpha[i] + rsum;
        }

        // write P tile; rescale accumulators
#pragma unroll
        for (int i = 0; i < 8; i++) {
#pragma unroll
            for (int j = 0; j < 4; j++)
                Ps[(ty * 8 + i) * FA_PITCH + tx * 4 + j] = s[i][j];
#pragma unroll
            for (int j = 0; j < 4; j++) acc[i][j] *= alpha[i];
        }
        __syncthreads();

        // O += P V  (8x4 per thread over e = tx*4..)
#pragma unroll 4
        for (int j = 0; j < 64; j++) {
            float pa[8], vb[4];
#pragma unroll
            for (int i = 0; i < 8; i++) pa[i] = Ps[(ty * 8 + i) * FA_PITCH + j];
#pragma unroll
            for (int e = 0; e < 4; e++) vb[e] = Vs[j * FA_PITCH + tx * 4 + e];
#pragma unroll
            for (int i = 0; i < 8; i++)
#pragma unroll
                for (int e = 0; e < 4; e++) acc[i][e] = fmaf(pa[i], vb[e], acc[i][e]);
        }
        __syncthreads();
    }

    // Epilogue: normalize and write ctx (concat-head layout)
#pragma unroll
    for (int i = 0; i < 8; i++) {
        float inv = 1.0f / lrow[i];
        int srow = sq0 + ty * 8 + i;
        size_t base = (((size_t)b << 10) + srow) * 1024 + (h << 6) + tx * 4;
#pragma unroll
        for (int e = 0; e < 4; e++) g_ctx[base + e] = acc[i][e] * inv;
    }
}

extern "C" void kernel_launch(void* const* d_in, const int* in_sizes, int n_in,
                              void* d_out, int out_size) {
    const float* x  = (const float*)d_in[0];
    const void*  mk = d_in[1];
    const float* Wq = (const float*)d_in[2];
    const float* bq = (const float*)d_in[3];
    const float* Wk = (const float*)d_in[4];
    const float* bk = (const float*)d_in[5];
    const float* Wv = (const float*)d_in[6];
    const float* bv = (const float*)d_in[7];
    const float* Wo = (const float*)d_in[8];
    const float* bo = (const float*)d_in[9];
    float* out = (float*)d_out;

    // raise dynamic smem limit for flash kernel (idempotent, capture-safe)
    static int smem_set = 0;
    if (!smem_set) {
        cudaFuncSetAttribute(flash_kernel, cudaFuncAttributeMaxDynamicSharedMemorySize,
                             FA_SMEM_FLOATS * 4);
        smem_set = 1;
    }

    // 1) mask dtype detection
    detect_mask_kernel<<<1, 256>>>((const int*)mk);

    // 2) pack QKV weights/biases
    repack_kernel<<<(3 * 1048576 + 255) / 256, 256>>>(Wq, bq, Wk, bk, Wv, bv);

    // 3) fused QKV projection: [8192x1024] x [1024x3072]
    sgemm128<<<dim3(3072 / 128, ROWS / 128), 256>>>(x, nullptr, nullptr, nullptr, 3072, 0);

    // 4) fused flash attention -> g_ctx
    flash_kernel<<<dim3(SEQ / 128, BHN), 256, FA_SMEM_FLOATS * 4>>>(
        (const unsigned char*)mk, (const int*)mk);

    // 5) output projection + bias -> d_out
    sgemm128<<<dim3(1024 / 128, ROWS / 128), 256>>>(nullptr, Wo, bo, out, 1024, 1);
}

// round 10
// speedup vs baseline: 1.4493x; 1.4493x over previous
#include <cuda_runtime.h>
#include <mma.h>
#include <math.h>

using namespace nvcuda;

// Problem constants
#define BATCH 8
#define SEQ   1024
#define DMODEL 1024
#define NHEAD 16
#define HDIM  64
#define BHN   (BATCH*NHEAD)         // 128
#define ROWS  (BATCH*SEQ)           // 8192

// -------- static device scratch (no runtime allocations allowed) --------
__device__ float g_Wqkv[1024*3072];          // 12 MB packed [D, 3*D], tf32-rounded
__device__ float g_bqkv[3072];
__device__ float g_x32[(size_t)ROWS*DMODEL]; // 32 MB tf32-rounded inputs
__device__ float g_Wo32[1024*1024];          // 4 MB tf32-rounded Wo
__device__ float g_Q[(size_t)BHN*SEQ*HDIM];  // 32 MB  [bh][s][e], fp32
__device__ float g_K[(size_t)BHN*SEQ*HDIM];  // 32 MB
__device__ float g_V[(size_t)BHN*SEQ*HDIM];  // 32 MB
__device__ float g_ctx[(size_t)ROWS*DMODEL]; // 32 MB  [b*S+s][h*64+e], tf32-rounded
__device__ int   g_mask_i32;                 // 1 if mask buffer is int32, 0 if uint8

// tf32 round-to-nearest-even, pure integer (no cvt instruction).
// Rounds away the low 13 mantissa bits. Valid for finite normal inputs.
__device__ __forceinline__ float to_tf32(float x) {
    unsigned int u = __float_as_uint(x);
    u = (u + 0xFFFu + ((u >> 13) & 1u)) & 0xFFFFE000u;
    return __uint_as_float(u);
}

// -------- mask dtype detection (deterministic, capture-safe) --------
__global__ void detect_mask_kernel(const int* __restrict__ m) {
    __shared__ int bad;
    if (threadIdx.x == 0) bad = 0;
    __syncthreads();
    int ok = 1;
    for (int i = threadIdx.x; i < 4096; i += 256) {
        int v = m[i];
        if (v != 0 && v != 1) ok = 0;
    }
    if (!ok) atomicOr(&bad, 1);
    __syncthreads();
    if (threadIdx.x == 0) g_mask_i32 = bad ? 0 : 1;
}

// -------- tf32 conversion into device-global scratch -------------------------
// NOTE: destination selected INSIDE device code. Passing a __device__ symbol as
// a host-side kernel argument takes the host-shadow address; on GB300 (ATS,
// pageableMemoryAccess=1) the kernel then silently writes host memory and the
// real device buffer stays zero. That was the R6-R9 bug.
__global__ void cvt_tf32_kernel(const float* __restrict__ in, int which, int n4) {
    float* out = which ? g_Wo32 : g_x32;
    int i = blockIdx.x * 256 + threadIdx.x;
    if (i < n4) {
        float4 v = ((const float4*)in)[i];
        v.x = to_tf32(v.x); v.y = to_tf32(v.y);
        v.z = to_tf32(v.z); v.w = to_tf32(v.w);
        ((float4*)out)[i] = v;
    }
}

// -------- repack Wq/Wk/Wv [H,D,DH] -> g_Wqkv [D, 3*D] (tf32), biases ---------
__global__ void repack_kernel(const float* __restrict__ Wq, const float* __restrict__ bq,
                              const float* __restrict__ Wk, const float* __restrict__ bk,
                              const float* __restrict__ Wv, const float* __restrict__ bv) {
    int idx = blockIdx.x * 256 + threadIdx.x;
    if (idx < 3 * 1048576) {
        int sel = idx >> 20;           // 0=Q,1=K,2=V
        int r   = idx & 1048575;
        int h = r >> 16;
        int r2 = r & 65535;
        int d = r2 >> 6;
        int e = r2 & 63;
        const float* W = (sel == 0) ? Wq : (sel == 1 ? Wk : Wv);
        g_Wqkv[(size_t)d * 3072 + (sel << 10) + (h << 6) + e] =
            to_tf32(W[(h << 16) + (d << 6) + e]);
    }
    if (idx < 3072) {
        int sel = idx >> 10;
        int jj = idx & 1023;
        const float* bb = (sel == 0) ? bq : (sel == 1 ? bk : bv);
        g_bqkv[idx] = bb[jj];
    }
}

// -------- tf32 WMMA GEMM: 128x128 block, 8 warps, warp = 32x64 (2x4 tiles) ---
// mode 0: A = g_x32 [8192x1024], B = g_Wqkv [1024x3072], bias = g_bqkv,
//         scatter into g_Q/g_K/g_V (fp32, [bh][s][e])
// mode 1: A = g_ctx [8192x1024], B = g_Wo32 [1024x1024], bias = biasext (bo),
//         C = Cext (d_out)
#define GB_BK 32
#define GB_AP 40
#define GB_BP 136

__global__ __launch_bounds__(256) void gemm_wmma(const float* __restrict__ biasext,
                                                 float* __restrict__ Cext,
                                                 int N, int mode) {
    __shared__ __align__(16) float As[128][GB_AP];
    __shared__ __align__(16) float Bs[GB_BK][GB_BP];
    __shared__ __align__(16) float BiasSm[16][GB_BP];

    const float* A = (mode == 0) ? g_x32 : g_ctx;
    const float* B = (mode == 0) ? g_Wqkv : g_Wo32;
    const float* bias = (mode == 0) ? g_bqkv : biasext;

    int tid = threadIdx.x;
    int warp = tid >> 5;
    int wm = warp >> 1;   // 0..3 -> 32-row slab
    int wn = warp & 1;    // 0..1 -> 64-col slab
    int row0 = blockIdx.y * 128, col0 = blockIdx.x * 128;

    // fill bias tile: 16 identical rows of bias[col0 .. col0+127]
    for (int i = tid; i < 16 * 128; i += 256) {
        int r = i >> 7, c = i & 127;
        BiasSm[r][c] = bias[col0 + c];
    }
    __syncthreads();

    // accumulators initialized with bias (broadcast across rows)
    wmma::fragment<wmma::accumulator, 16, 16, 8, float> acc[2][4];
#pragma unroll
    for (int mi = 0; mi < 2; mi++)
#pragma unroll
        for (int ni = 0; ni < 4; ni++)
            wmma::load_matrix_sync(acc[mi][ni], &BiasSm[0][wn * 64 + ni * 16], GB_BP,
                                   wmma::mem_row_major);

    for (int k0 = 0; k0 < 1024; k0 += GB_BK) {
        __syncthreads();
        // load As: 128 x 32 (4 float4 per thread)
#pragma unroll
        for (int l = 0; l < 4; l++) {
            int i = tid + l * 256;
            int r = i >> 3;                // 0..127
            int c = (i & 7) * 4;           // 0..28
            *(float4*)&As[r][c] = *(const float4*)(A + (size_t)(row0 + r) * 1024 + k0 + c);
        }
        // load Bs: 32 x 128 (4 float4 per thread)
#pragma unroll
        for (int l = 0; l < 4; l++) {
            int i = tid + l * 256;
            int r = i >> 5;                // 0..31
            int c = (i & 31) * 4;          // 0..124
            *(float4*)&Bs[r][c] = *(const float4*)(B + (size_t)(k0 + r) * N + col0 + c);
        }
        __syncthreads();

#pragma unroll
        for (int kk = 0; kk < GB_BK; kk += 8) {
            wmma::fragment<wmma::matrix_a, 16, 16, 8, wmma::precision::tf32,
                           wmma::row_major> af[2];
            wmma::fragment<wmma::matrix_b, 16, 16, 8, wmma::precision::tf32,
                           wmma::row_major> bf[4];
#pragma unroll
            for (int mi = 0; mi < 2; mi++)
                wmma::load_matrix_sync(af[mi], &As[wm * 32 + mi * 16][kk], GB_AP);
#pragma unroll
            for (int ni = 0; ni < 4; ni++)
                wmma::load_matrix_sync(bf[ni], &Bs[kk][wn * 64 + ni * 16], GB_BP);
#pragma unroll
            for (int mi = 0; mi < 2; mi++)
#pragma unroll
                for (int ni = 0; ni < 4; ni++)
                    wmma::mma_sync(acc[mi][ni], af[mi], bf[ni], acc[mi][ni]);
        }
    }

    // store: each 16x16 tile sits inside one head (64%16==0) and one batch (1024%16==0)
    if (mode == 0) {
        int sel = col0 >> 10;  // whole 128-col tile lies in one of Q/K/V
        float* dst = (sel == 0) ? g_Q : (sel == 1 ? g_K : g_V);
        int b = row0 >> 10;
#pragma unroll
        for (int mi = 0; mi < 2; mi++) {
            int r = row0 + wm * 32 + mi * 16;
            int s = r & 1023;
#pragma unroll
            for (int ni = 0; ni < 4; ni++) {
                int c = col0 + wn * 64 + ni * 16;
                int jj = c & 1023;
                int h = jj >> 6, e = jj & 63;
                wmma::store_matrix_sync(
                    &dst[((size_t)((b << 4) + h) << 16) + ((size_t)s << 6) + e],
                    acc[mi][ni], 64, wmma::mem_row_major);
            }
        }
    } else {
#pragma unroll
        for (int mi = 0; mi < 2; mi++) {
            int r = row0 + wm * 32 + mi * 16;
#pragma unroll
            for (int ni = 0; ni < 4; ni++) {
                int c = col0 + wn * 64 + ni * 16;
                wmma::store_matrix_sync(&Cext[(size_t)r * N + c], acc[mi][ni], N,
                                        wmma::mem_row_major);
            }
        }
    }
}

// -------- fused flash attention, fp32 ----------------------------------------
#define FA_PITCH 65
#define FA_SMEM_FLOATS (128*FA_PITCH + 64*FA_PITCH + 64*FA_PITCH + 128*FA_PITCH)

__global__ __launch_bounds__(256, 2) void flash_kernel(const unsigned char* __restrict__ m8,
                                                       const int* __restrict__ m32) {
    extern __shared__ float smf[];
    float* Qs = smf;                          // [128][65]
    float* Ks = Qs + 128 * FA_PITCH;          // [64][65]
    float* Vs = Ks + 64 * FA_PITCH;           // [64][65]
    float* Ps = Vs + 64 * FA_PITCH;           // [128][65]

    int tid = threadIdx.x;
    int tx = tid & 15;
    int ty = tid >> 4;
    int bh = blockIdx.y;
    int b = bh >> 4, h = bh & 15;
    int sq0 = blockIdx.x * 128;

    const float* Qp = g_Q + (size_t)bh * 65536;
    const float* Kp = g_K + (size_t)bh * 65536;
    const float* Vp = g_V + (size_t)bh * 65536;
    int mi32 = g_mask_i32;

#pragma unroll
    for (int l = 0; l < 8; l++) {
        int idx = tid + l * 256;
        int r = idx >> 4;
        int c = (idx & 15) * 4;
        float4 v = *(const float4*)(Qp + (size_t)(sq0 + r) * 64 + c);
        float* dq = Qs + r * FA_PITCH + c;
        dq[0] = v.x; dq[1] = v.y; dq[2] = v.z; dq[3] = v.w;
    }

    float acc[8][4];
    float mrow[8], lrow[8];
#pragma unroll
    for (int i = 0; i < 8; i++) {
        mrow[i] = -INFINITY; lrow[i] = 0.f;
#pragma unroll
        for (int j = 0; j < 4; j++) acc[i][j] = 0.f;
    }

    for (int sk0 = 0; sk0 < SEQ; sk0 += 64) {
#pragma unroll
        for (int l = 0; l < 4; l++) {
            int idx = tid + l * 256;
            int r = idx >> 4;
            int c = (idx & 15) * 4;
            float4 kv = *(const float4*)(Kp + (size_t)(sk0 + r) * 64 + c);
            float* dk = Ks + r * FA_PITCH + c;
            dk[0] = kv.x; dk[1] = kv.y; dk[2] = kv.z; dk[3] = kv.w;
            float4 vv = *(const float4*)(Vp + (size_t)(sk0 + r) * 64 + c);
            float* dv = Vs + r * FA_PITCH + c;
            dv[0] = vv.x; dv[1] = vv.y; dv[2] = vv.z; dv[3] = vv.w;
        }
        __syncthreads();

        float s[8][4];
#pragma unroll
        for (int i = 0; i < 8; i++)
#pragma unroll
            for (int j = 0; j < 4; j++) s[i][j] = 0.f;
#pragma unroll 4
        for (int e = 0; e < 64; e++) {
            float qa[8], kb[4];
#pragma unroll
            for (int i = 0; i < 8; i++) qa[i] = Qs[(ty * 8 + i) * FA_PITCH + e];
#pragma unroll
            for (int j = 0; j < 4; j++) kb[j] = Ks[(tx * 4 + j) * FA_PITCH + e];
#pragma unroll
            for (int i = 0; i < 8; i++)
#pragma unroll
                for (int j = 0; j < 4; j++) s[i][j] = fmaf(qa[i], kb[j], s[i][j]);
        }

        const float scale = 0.03125f;  // 1/sqrt(1024)
        float alpha[8];
#pragma unroll
        for (int i = 0; i < 8; i++) {
            size_t midx = ((size_t)b << 20) + ((size_t)(sq0 + ty * 8 + i) << 10) + sk0 + tx * 4;
            int mv[4];
            if (mi32) {
                int4 mm = *(const int4*)(m32 + midx);
                mv[0] = mm.x; mv[1] = mm.y; mv[2] = mm.z; mv[3] = mm.w;
            } else {
                uchar4 mm = *(const uchar4*)(m8 + midx);
                mv[0] = mm.x; mv[1] = mm.y; mv[2] = mm.z; mv[3] = mm.w;
            }
#pragma unroll
            for (int j = 0; j < 4; j++) s[i][j] = mv[j] ? -1e9f : s[i][j] * scale;

            float rmax = fmaxf(fmaxf(s[i][0], s[i][1]), fmaxf(s[i][2], s[i][3]));
#pragma unroll
            for (int o = 1; o < 16; o <<= 1)
                rmax = fmaxf(rmax, __shfl_xor_sync(0xFFFFFFFFu, rmax, o));
            float mnew = fmaxf(mrow[i], rmax);
            alpha[i] = __expf(mrow[i] - mnew);
            mrow[i] = mnew;
            float rsum = 0.f;
#pragma unroll
            for (int j = 0; j < 4; j++) {
                s[i][j] = __expf(s[i][j] - mnew);
                rsum += s[i][j];
            }
#pragma unroll
            for (int o = 1; o < 16; o <<= 1)
                rsum += __shfl_xor_sync(0xFFFFFFFFu, rsum, o);
            lrow[i] = lrow[i] * alpha[i] + rsum;
        }

#pragma unroll
        for (int i = 0; i < 8; i++) {
#pragma unroll
            for (int j = 0; j < 4; j++)
                Ps[(ty * 8 + i) * FA_PITCH + tx * 4 + j] = s[i][j];
#pragma unroll
            for (int j = 0; j < 4; j++) acc[i][j] *= alpha[i];
        }
        __syncthreads();

#pragma unroll 4
        for (int j = 0; j < 64; j++) {
            float pa[8], vb[4];
#pragma unroll
            for (int i = 0; i < 8; i++) pa[i] = Ps[(ty * 8 + i) * FA_PITCH + j];
#pragma unroll
            for (int e = 0; e < 4; e++) vb[e] = Vs[j * FA_PITCH + tx * 4 + e];
#pragma unroll
            for (int i = 0; i < 8; i++)
#pragma unroll
                for (int e = 0; e < 4; e++) acc[i][e] = fmaf(pa[i], vb[e], acc[i][e]);
        }
        __syncthreads();
    }

    // Epilogue: normalize, round to tf32 (feeds the tf32 output GEMM), write ctx
#pragma unroll
    for (int i = 0; i < 8; i++) {
        float inv = 1.0f / lrow[i];
        int srow = sq0 + ty * 8 + i;
        size_t base = (((size_t)b << 10) + srow) * 1024 + (h << 6) + tx * 4;
#pragma unroll
        for (int e = 0; e < 4; e++) g_ctx[base + e] = to_tf32(acc[i][e] * inv);
    }
}

extern "C" void kernel_launch(void* const* d_in, const int* in_sizes, int n_in,
                              void* d_out, int out_size) {
    const float* x  = (const float*)d_in[0];
    const void*  mk = d_in[1];
    const float* Wq = (const float*)d_in[2];
    const float* bq = (const float*)d_in[3];
    const float* Wk = (const float*)d_in[4];
    const float* bk = (const float*)d_in[5];
    const float* Wv = (const float*)d_in[6];
    const float* bv = (const float*)d_in[7];
    const float* Wo = (const float*)d_in[8];
    const float* bo = (const float*)d_in[9];
    float* out = (float*)d_out;

    // idempotent, deterministic, safe during capture (not a stream op)
    cudaFuncSetAttribute(flash_kernel, cudaFuncAttributeMaxDynamicSharedMemorySize,
                         FA_SMEM_FLOATS * 4);

    // 1) mask dtype detection
    detect_mask_kernel<<<1, 256>>>((const int*)mk);

    // 2) tf32 conversions + weight pack (destinations resolved in device code)
    cvt_tf32_kernel<<<(ROWS * DMODEL / 4 + 255) / 256, 256>>>(x, 0, ROWS * DMODEL / 4);
    cvt_tf32_kernel<<<(1024 * 1024 / 4 + 255) / 256, 256>>>(Wo, 1, 1024 * 1024 / 4);
    repack_kernel<<<(3 * 1048576 + 255) / 256, 256>>>(Wq, bq, Wk, bk, Wv, bv);

    // 3) fused QKV projection (wmma tf32): [8192x1024] x [1024x3072]
    gemm_wmma<<<dim3(3072 / 128, ROWS / 128), 256>>>(nullptr, nullptr, 3072, 0);

    // 4) fused flash attention -> g_ctx
    flash_kernel<<<dim3(SEQ / 128, BHN), 256, FA_SMEM_FLOATS * 4>>>(
        (const unsigned char*)mk, (const int*)mk);

    // 5) output projection + bias -> d_out (wmma tf32)
    gemm_wmma<<<dim3(1024 / 128, ROWS / 128), 256>>>(bo, out, 1024, 1);
}